// round 4
// baseline (speedup 1.0000x reference)
#include <cuda_runtime.h>

// Guided filter, RADIUS=8, EPS=0.01, (8,3,1024,1024) fp32.
// Two fused kernels (horizontal box + vertical sliding box, trail recompute).
// Horizontal box sums are computed WARP-COOPERATIVELY: each lane loads only
// its own 8 columns; halo data moves via warp shuffles (prefix-scan identity
// box[c] = P[c+8] - P[c-9]) instead of overlapping L1 window reads.

#define W     1024
#define Hh    1024
#define IMGS  24
#define HW    (Hh * W)
#define TOTAL (IMGS * HW)
#define RAD   8
#define EPSF  0.01f
#define SEGR  32
#define SEGS  (Hh / SEGR)
#define TPB   128               // 4 warps; warp w owns cols [256w, 256w+255]
#define FULLM 0xffffffffu

__device__ __align__(16) float g_a[TOTAL];
__device__ __align__(16) float g_b[TOTAL];

// Load own 8 cols of one row + halo: lane 0 keeps the 8 cols left of the warp
// strip in h[], lane 31 the 8 cols right of it (zero if outside image).
__device__ __forceinline__ void load_strip(const float* __restrict__ r, int C,
                                           int lane, float v[8], float h[8]) {
    int col0 = C + lane * 8;
    float4 p0 = *(const float4*)(r + col0);
    float4 p1 = *(const float4*)(r + col0 + 4);
    v[0]=p0.x; v[1]=p0.y; v[2]=p0.z; v[3]=p0.w;
    v[4]=p1.x; v[5]=p1.y; v[6]=p1.z; v[7]=p1.w;
    #pragma unroll
    for (int j = 0; j < 8; j++) h[j] = 0.0f;
    if (lane == 0) {
        if (C > 0) {
            float4 a = *(const float4*)(r + C - 8);
            float4 b = *(const float4*)(r + C - 4);
            h[0]=a.x; h[1]=a.y; h[2]=a.z; h[3]=a.w;
            h[4]=b.x; h[5]=b.y; h[6]=b.z; h[7]=b.w;
        }
    } else if (lane == 31) {
        if (C + 256 < W) {
            float4 a = *(const float4*)(r + C + 256);
            float4 b = *(const float4*)(r + C + 260);
            h[0]=a.x; h[1]=a.y; h[2]=a.z; h[3]=a.w;
            h[4]=b.x; h[5]=b.y; h[6]=b.z; h[7]=b.w;
        }
    }
}

// Resolve neighbor values: vn[j] = value at col0+8+j (right neighbor / right
// halo for lane 31), vp[j] (j>=1) = value at col0+j-9 (left neighbor / left
// halo for lane 0).
__device__ __forceinline__ void neigh(const float v[8], const float h[8], int lane,
                                      float vn[8], float vp[8]) {
    #pragma unroll
    for (int j = 0; j < 8; j++) vn[j] = __shfl_down_sync(FULLM, v[j], 1);
    vp[0] = 0.0f;
    #pragma unroll
    for (int j = 1; j < 8; j++) vp[j] = __shfl_up_sync(FULLM, v[j - 1], 1);
    if (lane == 31) {
        #pragma unroll
        for (int j = 0; j < 8; j++) vn[j] = h[j];
    }
    if (lane == 0) {
        #pragma unroll
        for (int j = 1; j < 8; j++) vp[j] = h[j - 1];
    }
}

// Core: given per-lane series total `tot` and halo-sum `hs` (valid on lane 0),
// produce the 17-wide box sums via warp scan and accumulate into s[8].
template<int SGN>
__device__ __forceinline__ void box_core(float tot, float hs, int lane,
                                         const float vn0, const float* dif, // dif[j]=vn[j]-vp[j], j=1..7
                                         float s[8]) {
    float incl = tot;
    #pragma unroll
    for (int d = 1; d < 32; d <<= 1) {
        float n = __shfl_up_sync(FULLM, incl, d);
        if (lane >= d) incl += n;
    }
    float Bprev = __shfl_up_sync(FULLM, incl - tot, 1);  // P[col0-9]
    if (lane == 0) Bprev = -hs;
    float b = incl + vn0 - Bprev;
    if (SGN > 0) s[0] += b; else s[0] -= b;
    #pragma unroll
    for (int j = 1; j < 8; j++) {
        b += dif[j];
        if (SGN > 0) s[j] += b; else s[j] -= b;
    }
}

template<int SGN>
__device__ __forceinline__ void box_plain(const float v[8], const float vn[8],
                                          const float vp[8], const float h[8],
                                          int lane, float s[8]) {
    float tot = ((v[0]+v[1])+(v[2]+v[3])) + ((v[4]+v[5])+(v[6]+v[7]));
    float hs  = ((h[0]+h[1])+(h[2]+h[3])) + ((h[4]+h[5])+(h[6]+h[7]));
    float dif[8];
    #pragma unroll
    for (int j = 1; j < 8; j++) dif[j] = vn[j] - vp[j];
    box_core<SGN>(tot, hs, lane, vn[0], dif, s);
}

template<int SGN>
__device__ __forceinline__ void box_sq(const float v[8], const float vn[8],
                                       const float vp[8], const float h[8],
                                       int lane, float s[8]) {
    float tot = 0.f, hs = 0.f;
    #pragma unroll
    for (int j = 0; j < 8; j++) { tot = fmaf(v[j], v[j], tot); hs = fmaf(h[j], h[j], hs); }
    float dif[8];
    #pragma unroll
    for (int j = 1; j < 8; j++) dif[j] = vn[j]*vn[j] - vp[j]*vp[j];
    box_core<SGN>(tot, hs, lane, vn[0]*vn[0], dif, s);
}

template<int SGN>
__device__ __forceinline__ void box_prod(const float va[8], const float vna[8], const float vpa[8],
                                         const float vb[8], const float vnb[8], const float vpb[8],
                                         const float ha[8], const float hb[8],
                                         int lane, float s[8]) {
    float tot = 0.f, hs = 0.f;
    #pragma unroll
    for (int j = 0; j < 8; j++) { tot = fmaf(va[j], vb[j], tot); hs = fmaf(ha[j], hb[j], hs); }
    float dif[8];
    #pragma unroll
    for (int j = 1; j < 8; j++) dif[j] = vna[j]*vnb[j] - vpa[j]*vpb[j];
    box_core<SGN>(tot, hs, lane, vna[0]*vnb[0], dif, s);
}

// One row-visit for stage A: accumulate h-box of {x, y, xx, xy}.
template<int SGN>
__device__ __forceinline__ void visitA(const float* __restrict__ xr,
                                       const float* __restrict__ yr,
                                       int C, int lane,
                                       float s0[8], float s1[8],
                                       float s2[8], float s3[8]) {
    float vx[8], hx[8], vy[8], hy[8];
    load_strip(xr, C, lane, vx, hx);
    load_strip(yr, C, lane, vy, hy);
    float vnx[8], vpx[8], vny[8], vpy[8];
    neigh(vx, hx, lane, vnx, vpx);
    neigh(vy, hy, lane, vny, vpy);
    box_plain<SGN>(vx, vnx, vpx, hx, lane, s0);
    box_plain<SGN>(vy, vny, vpy, hy, lane, s1);
    box_sq   <SGN>(vx, vnx, vpx, hx, lane, s2);
    box_prod <SGN>(vx, vnx, vpx, vy, vny, vpy, hx, hy, lane, s3);
}

// One row-visit for stage B: accumulate h-box of {a, b}.
template<int SGN>
__device__ __forceinline__ void visitB(const float* __restrict__ ar,
                                       const float* __restrict__ br,
                                       int C, int lane,
                                       float sa[8], float sb[8]) {
    float va[8], ha[8], vb[8], hb[8];
    load_strip(ar, C, lane, va, ha);
    load_strip(br, C, lane, vb, hb);
    float vna[8], vpa[8], vnb[8], vpb[8];
    neigh(va, ha, lane, vna, vpa);
    neigh(vb, hb, lane, vnb, vpb);
    box_plain<SGN>(va, vna, vpa, ha, lane, sa);
    box_plain<SGN>(vb, vnb, vpb, hb, lane, sb);
}

// ---------------------------------------------------------------------------
__global__ void __launch_bounds__(TPB) kA(const float* __restrict__ x,
                                          const float* __restrict__ y) {
    int img  = blockIdx.y;
    int s    = blockIdx.x * SEGR;
    int warp = threadIdx.x >> 5;
    int lane = threadIdx.x & 31;
    int C    = warp << 8;
    int col0 = C + lane * 8;
    const float* xb = x + img * HW;
    const float* yb = y + img * HW;

    float s0[8], s1[8], s2[8], s3[8];
    #pragma unroll
    for (int j = 0; j < 8; j++) { s0[j]=0.f; s1[j]=0.f; s2[j]=0.f; s3[j]=0.f; }

    for (int r = max(0, s - RAD); r <= s + RAD; r++)
        visitA<+1>(xb + r * W, yb + r * W, C, lane, s0, s1, s2, s3);

    float nxv[8];
    #pragma unroll
    for (int j = 0; j < 8; j++) {
        int c = col0 + j;
        nxv[j] = (float)(min(W - 1, c + RAD) - max(0, c - RAD) + 1);
    }

    float* ga = g_a + img * HW;
    float* gb = g_b + img * HW;

    for (int o = s; o < s + SEGR; o++) {
        float ny = (float)(min(Hh - 1, o + RAD) - max(0, o - RAD) + 1);
        float ra[8], rb[8];
        #pragma unroll
        for (int j = 0; j < 8; j++) {
            float invN = __frcp_rn(nxv[j] * ny);
            float mx = s0[j] * invN, my = s1[j] * invN;
            float varx = fmaf(-mx, mx, s2[j] * invN);
            float cov  = fmaf(-mx, my, s3[j] * invN);
            float a = __fdividef(cov, varx + EPSF);
            ra[j] = a;
            rb[j] = fmaf(-a, mx, my);
        }
        #pragma unroll
        for (int q = 0; q < 2; q++) {
            float4 av, bv;
            av.x = ra[4*q+0]; av.y = ra[4*q+1]; av.z = ra[4*q+2]; av.w = ra[4*q+3];
            bv.x = rb[4*q+0]; bv.y = rb[4*q+1]; bv.z = rb[4*q+2]; bv.w = rb[4*q+3];
            *(float4*)(ga + o * W + col0 + 4*q) = av;
            *(float4*)(gb + o * W + col0 + 4*q) = bv;
        }

        int lead = o + RAD + 1, trail = o - RAD;
        if (lead < Hh)
            visitA<+1>(xb + lead * W, yb + lead * W, C, lane, s0, s1, s2, s3);
        if (trail >= 0)
            visitA<-1>(xb + trail * W, yb + trail * W, C, lane, s0, s1, s2, s3);
    }
}

// ---------------------------------------------------------------------------
__global__ void __launch_bounds__(TPB) kB(const float* __restrict__ x,
                                          float* __restrict__ out) {
    int img  = blockIdx.y;
    int s    = blockIdx.x * SEGR;
    int warp = threadIdx.x >> 5;
    int lane = threadIdx.x & 31;
    int C    = warp << 8;
    int col0 = C + lane * 8;
    const float* ab = g_a + img * HW;
    const float* bb = g_b + img * HW;
    const float* xb = x + img * HW;
    float* ob = out + img * HW;

    float sa[8], sb[8];
    #pragma unroll
    for (int j = 0; j < 8; j++) { sa[j]=0.f; sb[j]=0.f; }

    for (int r = max(0, s - RAD); r <= s + RAD; r++)
        visitB<+1>(ab + r * W, bb + r * W, C, lane, sa, sb);

    float nxv[8];
    #pragma unroll
    for (int j = 0; j < 8; j++) {
        int c = col0 + j;
        nxv[j] = (float)(min(W - 1, c + RAD) - max(0, c - RAD) + 1);
    }

    for (int o = s; o < s + SEGR; o++) {
        float ny = (float)(min(Hh - 1, o + RAD) - max(0, o - RAD) + 1);
        #pragma unroll
        for (int q = 0; q < 2; q++) {
            float4 xv = *(const float4*)(xb + o * W + col0 + 4*q);
            float xs[4] = {xv.x, xv.y, xv.z, xv.w};
            float os[4];
            #pragma unroll
            for (int j = 0; j < 4; j++) {
                int k = 4*q + j;
                float invN = __frcp_rn(nxv[k] * ny);
                os[j] = fmaf(sa[k] * invN, xs[j], sb[k] * invN);
            }
            float4 ov;
            ov.x = os[0]; ov.y = os[1]; ov.z = os[2]; ov.w = os[3];
            *(float4*)(ob + o * W + col0 + 4*q) = ov;
        }

        int lead = o + RAD + 1, trail = o - RAD;
        if (lead < Hh)
            visitB<+1>(ab + lead * W, bb + lead * W, C, lane, sa, sb);
        if (trail >= 0)
            visitB<-1>(ab + trail * W, bb + trail * W, C, lane, sa, sb);
    }
}

extern "C" void kernel_launch(void* const* d_in, const int* in_sizes, int n_in,
                              void* d_out, int out_size) {
    const float* x = (const float*)d_in[0];
    const float* y = (const float*)d_in[1];
    float* out = (float*)d_out;

    dim3 grid(SEGS, IMGS);
    kA<<<grid, TPB>>>(x, y);
    kB<<<grid, TPB>>>(x, out);
}